// round 5
// baseline (speedup 1.0000x reference)
#include <cuda_runtime.h>
#include <cuda_bf16.h>

// ============================================================================
// Problem constants
// ============================================================================
#define T_STEPS 128
#define BS      64
#define NP      64      // particles
#define H       256
#define OUTD    64
#define M_ROWS  (BS*NP)             // 4096 rows per state GEMM
#define STATE_ELEMS (BS*NP*H)       // 1048576

// Dynamic smem layout for GEMM kernels:
//   Bs  [256][68] floats  (full B tile, resident)
//   As2 [2][16][132] floats (A chunks, values duplicated for f32x2)
#define BS_FLOATS   (256*68)        // 17408
#define AS2_FLOATS  (2*16*132)      // 4224
#define SMEM_BYTES  ((BS_FLOATS + AS2_FLOATS)*4)  // 86528

// ============================================================================
// Device scratch (static allocations only — no cudaMalloc allowed)
// ============================================================================
__device__ float g_x[STATE_ELEMS];        // particle state x  [BS*NP, H]
__device__ float g_h[STATE_ELEMS];        // h (post tanh+noise)
__device__ float g_act[STATE_ELEMS];      // FFN hidden activation
__device__ float g_proj[T_STEPS*BS*H];    // u @ W_ih^T + b_ih for all t
__device__ float g_sxstd[H];              // sqrt(sigma_x_diag)
__device__ float g_logdet;                // 0.5*sum(log sy) + 0.5*OUT*log2pi
__device__ unsigned g_keybits[512];       // split-foldlike keys: key j = ([2j],[2j+1])
__device__ unsigned g_x0key[2];           // fold_in(key, 0)

// ============================================================================
// JAX Threefry-2x32 (exact replication, partitionable mode)
// ============================================================================
__device__ __forceinline__ unsigned rotl32(unsigned v, int d) {
    return __funnelshift_l(v, v, d);
}

__device__ __forceinline__ void threefry2x32(unsigned k0, unsigned k1,
                                             unsigned x, unsigned y,
                                             unsigned &o0, unsigned &o1) {
    unsigned k2 = k0 ^ k1 ^ 0x1BD11BDAu;
    x += k0; y += k1;
#define TF_R(r) { x += y; y = rotl32(y, (r)); y ^= x; }
    TF_R(13) TF_R(15) TF_R(26) TF_R(6)
    x += k1; y += k2 + 1u;
    TF_R(17) TF_R(29) TF_R(16) TF_R(24)
    x += k2; y += k0 + 2u;
    TF_R(13) TF_R(15) TF_R(26) TF_R(6)
    x += k0; y += k1 + 3u;
    TF_R(17) TF_R(29) TF_R(16) TF_R(24)
    x += k1; y += k2 + 4u;
    TF_R(13) TF_R(15) TF_R(26) TF_R(6)
    x += k2; y += k0 + 5u;
#undef TF_R
    o0 = x; o1 = y;
}

__device__ __forceinline__ unsigned jax_random_bits32(unsigned k0, unsigned k1,
                                                      unsigned i) {
    unsigned a, b;
    threefry2x32(k0, k1, 0u, i, a, b);
    return a ^ b;
}

// ============================================================================
// XLA-exact elementwise ops (plain mul/add, no FMA contraction — matches
// XLA's LLVM emission which does not set contract fast-math flags)
// ============================================================================
__device__ __forceinline__ float bits_to_unit(unsigned b) {
    return __fsub_rn(__uint_as_float((b >> 9) | 0x3f800000u), 1.0f);
}

// XLA EmitErfInv f32 (Giles): w = -log((1-x)*(1+x)), mul/add Horner
__device__ __forceinline__ float erfinv_xla(float x) {
    float w = -logf(__fmul_rn(__fsub_rn(1.0f, x), __fadd_rn(1.0f, x)));
    float p;
    if (w < 5.0f) {
        w = __fsub_rn(w, 2.5f);
        p = 2.81022636e-08f;
        p = __fadd_rn(3.43273939e-07f,  __fmul_rn(p, w));
        p = __fadd_rn(-3.5233877e-06f,  __fmul_rn(p, w));
        p = __fadd_rn(-4.39150654e-06f, __fmul_rn(p, w));
        p = __fadd_rn(0.00021858087f,   __fmul_rn(p, w));
        p = __fadd_rn(-0.00125372503f,  __fmul_rn(p, w));
        p = __fadd_rn(-0.00417768164f,  __fmul_rn(p, w));
        p = __fadd_rn(0.246640727f,     __fmul_rn(p, w));
        p = __fadd_rn(1.50140941f,      __fmul_rn(p, w));
    } else {
        w = __fsub_rn(sqrtf(w), 3.0f);
        p = -0.000200214257f;
        p = __fadd_rn(0.000100950558f,  __fmul_rn(p, w));
        p = __fadd_rn(0.00134934322f,   __fmul_rn(p, w));
        p = __fadd_rn(-0.00367342844f,  __fmul_rn(p, w));
        p = __fadd_rn(0.00573950773f,   __fmul_rn(p, w));
        p = __fadd_rn(-0.0076224613f,   __fmul_rn(p, w));
        p = __fadd_rn(0.00943887047f,   __fmul_rn(p, w));
        p = __fadd_rn(1.00167406f,      __fmul_rn(p, w));
        p = __fadd_rn(2.83297682f,      __fmul_rn(p, w));
    }
    return __fmul_rn(p, x);
}

__device__ __forceinline__ float jax_normal_from_bits(unsigned b) {
    float f = bits_to_unit(b);
    // uniform(lo=nextafter(-1,0), hi=1): (hi-lo) == 2.0f exactly; f*2 exact
    float u = __fadd_rn(__fmul_rn(f, 2.0f), -0.99999994f);
    u = fmaxf(u, -0.99999994f);
    return __fmul_rn(1.41421354f, erfinv_xla(u));
}

__device__ __forceinline__ float jax_gumbel_from_bits(unsigned b) {
    float f = bits_to_unit(b);
    float u = fmaxf(1.17549435e-38f, __fadd_rn(f, 1.17549435e-38f));
    return -logf(-logf(u));
}

// XLA GpuElementalIrEmitter::EmitTanh f32 = EmitFastTanh (Eigen rational):
// |x| < 0.0004 -> x; else rational poly on x clamped to [-9, 9].
__device__ __forceinline__ float xla_tanh(float x) {
    float ax = fabsf(x);
    float xc = fminf(fmaxf(x, -9.0f), 9.0f);
    float x2 = __fmul_rn(xc, xc);
    float p = -2.76076847742355e-16f;
    p = __fadd_rn(2.00018790482477e-13f, __fmul_rn(p, x2));
    p = __fadd_rn(-8.60467152213735e-11f, __fmul_rn(p, x2));
    p = __fadd_rn(5.12229709037114e-08f,  __fmul_rn(p, x2));
    p = __fadd_rn(1.48572235717979e-05f,  __fmul_rn(p, x2));
    p = __fadd_rn(6.37261928875436e-04f,  __fmul_rn(p, x2));
    p = __fadd_rn(4.89352455891786e-03f,  __fmul_rn(p, x2));
    float num = __fmul_rn(xc, p);
    float q = 1.19825839466702e-06f;
    q = __fadd_rn(1.18534705686654e-04f, __fmul_rn(q, x2));
    q = __fadd_rn(2.26843463243900e-03f, __fmul_rn(q, x2));
    q = __fadd_rn(4.89352518554385e-03f, __fmul_rn(q, x2));
    float r = __fdiv_rn(num, q);
    return (ax < 0.0004f) ? x : r;
}

// ============================================================================
// Packed fp32x2 FMA (two IEEE-rn FMAs per instruction)
// ============================================================================
__device__ __forceinline__ void fma2(unsigned long long &d,
                                     unsigned long long a,
                                     unsigned long long b) {
    asm("fma.rn.f32x2 %0, %1, %2, %0;" : "+l"(d) : "l"(a), "l"(b));
}
__device__ __forceinline__ void unpack2(unsigned long long v, float &lo, float &hi) {
    asm("mov.b64 {%0, %1}, %2;" : "=f"(lo), "=f"(hi) : "l"(v));
}

// ============================================================================
// Key / scale / logdet preparation
// ============================================================================
__global__ void prep_kernel(const float* __restrict__ sx,
                            const float* __restrict__ sy) {
    int i = threadIdx.x;   // 256 threads
    if (i < H) g_sxstd[i] = sqrtf(sx[i]);
    unsigned sb0, sb1;
    threefry2x32(0u, 42u, 0u, 1u, sb0, sb1);           // fold_in(key,1)
    unsigned o0, o1;
    threefry2x32(sb0, sb1, 0u, (unsigned)i, o0, o1);   // split-foldlike
    g_keybits[2*i]     = o0;
    g_keybits[2*i + 1] = o1;
    if (i == 0) {
        unsigned a, b;
        threefry2x32(0u, 42u, 0u, 0u, a, b);           // fold_in(key,0)
        g_x0key[0] = a; g_x0key[1] = b;
    }
    // logdet: XLA row-reduce pattern (lane + lane+32, shfl tree)
    if (i < 32) {
        float s = __fadd_rn(logf(sy[i]), logf(sy[i + 32]));
#pragma unroll
        for (int off = 16; off; off >>= 1)
            s = __fadd_rn(s, __shfl_down_sync(0xffffffffu, s, off));
        if (i == 0) {
            float t2 = __fmul_rn(32.0f, 1.8378770351409912f);  // 0.5*64*log2pi(f32)
            g_logdet = __fadd_rn(__fmul_rn(0.5f, s), t2);
        }
    }
}

__global__ void x0_kernel() {
    int i = blockIdx.x * blockDim.x + threadIdx.x;     // < 1048576
    unsigned bits = jax_random_bits32(g_x0key[0], g_x0key[1], (unsigned)i);
    g_x[i] = jax_normal_from_bits(bits);
}

// ============================================================================
// GEMM core: C_tile[64x64] = A[M,256] * B, 256 threads, 4x4 per thread,
// full B tile resident in smem, A double-buffered in 16-k chunks,
// packed f32x2 FMA, ascending-k serial accumulation per output element.
// BT = true : B is [N,256] row-major (C = A * B^T)
// BT = false: B is [256,N] row-major (C = A * B), leading dim ldb
// ============================================================================
template<bool BT>
__device__ __forceinline__ void gemm_core(const float* __restrict__ A,
                                          const float* __restrict__ B,
                                          int ldb, float* smem,
                                          unsigned long long accp[4][2]) {
    float* Bsm = smem;                 // [256][68]
    float* As2 = smem + BS_FLOATS;     // [2][16][132]
    int tid = threadIdx.x;

    if (BT) {
#pragma unroll
        for (int it = 0; it < 16; it++) {
            int l = tid + 256 * it;        // 0..4095
            int n = l & 63;
            int kq = (l >> 6) << 2;        // 0..252
            float4 v = *(const float4*)(B + (size_t)(blockIdx.y*64 + n)*256 + kq);
            Bsm[(kq+0)*68 + n] = v.x; Bsm[(kq+1)*68 + n] = v.y;
            Bsm[(kq+2)*68 + n] = v.z; Bsm[(kq+3)*68 + n] = v.w;
        }
    } else {
#pragma unroll
        for (int it = 0; it < 16; it++) {
            int l = tid + 256 * it;
            int k = l >> 4;                // 0..255
            int nq = (l & 15) << 2;        // 0..60
            float4 v = *(const float4*)(B + (size_t)k*ldb + blockIdx.y*64 + nq);
            *(float4*)&Bsm[k*68 + nq] = v;
        }
    }

    int arow = tid >> 2;               // 0..63
    int akq  = (tid & 3) << 2;         // 0,4,8,12
    const float* Ap = A + (size_t)(blockIdx.x*64 + arow)*256 + akq;
    int ty = tid >> 4, tx = tid & 15;

    {
        float4 av = *(const float4*)(Ap);
        float* d = As2;
        *(float2*)&d[(akq+0)*132 + arow*2] = make_float2(av.x, av.x);
        *(float2*)&d[(akq+1)*132 + arow*2] = make_float2(av.y, av.y);
        *(float2*)&d[(akq+2)*132 + arow*2] = make_float2(av.z, av.z);
        *(float2*)&d[(akq+3)*132 + arow*2] = make_float2(av.w, av.w);
    }
    __syncthreads();

    for (int c = 0; c < 16; c++) {
        float4 nv;
        if (c + 1 < 16) nv = *(const float4*)(Ap + (c+1)*16);
        const float* As = As2 + (c & 1) * (16*132);
        const float* Bc = Bsm + c * 16 * 68;   // absolute-k chunk offset
#pragma unroll
        for (int k = 0; k < 16; k++) {
            ulonglong2 bp  = *(const ulonglong2*)&Bc[k*68 + tx*4];
            ulonglong2 ad0 = *(const ulonglong2*)&As[k*132 + ty*8];
            ulonglong2 ad1 = *(const ulonglong2*)&As[k*132 + ty*8 + 4];
            fma2(accp[0][0], ad0.x, bp.x); fma2(accp[0][1], ad0.x, bp.y);
            fma2(accp[1][0], ad0.y, bp.x); fma2(accp[1][1], ad0.y, bp.y);
            fma2(accp[2][0], ad1.x, bp.x); fma2(accp[2][1], ad1.x, bp.y);
            fma2(accp[3][0], ad1.y, bp.x); fma2(accp[3][1], ad1.y, bp.y);
        }
        if (c + 1 < 16) {
            float* d = As2 + ((c+1) & 1) * (16*132);
            *(float2*)&d[(akq+0)*132 + arow*2] = make_float2(nv.x, nv.x);
            *(float2*)&d[(akq+1)*132 + arow*2] = make_float2(nv.y, nv.y);
            *(float2*)&d[(akq+2)*132 + arow*2] = make_float2(nv.z, nv.z);
            *(float2*)&d[(akq+3)*132 + arow*2] = make_float2(nv.w, nv.w);
        }
        __syncthreads();
    }
}

__device__ __forceinline__ void unpack_acc(unsigned long long accp[4][2],
                                           float acc[4][4]) {
#pragma unroll
    for (int i = 0; i < 4; i++) {
        unpack2(accp[i][0], acc[i][0], acc[i][1]);
        unpack2(accp[i][1], acc[i][2], acc[i][3]);
    }
}

// ============================================================================
// proj[t,b,:] = u[t,b,:] @ W_ih^T + b_ih  (M = T*BS = 8192)
// ============================================================================
__global__ void __launch_bounds__(256, 2)
proj_kernel(const float* __restrict__ u, const float* __restrict__ W_ih,
            const float* __restrict__ b_ih) {
    extern __shared__ float smem[];
    unsigned long long accp[4][2] = {};
    gemm_core<true>(u, W_ih, H, smem, accp);
    float acc[4][4]; unpack_acc(accp, acc);
    int tx = threadIdx.x & 15, ty = threadIdx.x >> 4;
    int row0 = blockIdx.x * 64 + ty * 4;
    int col0 = blockIdx.y * 64 + tx * 4;
#pragma unroll
    for (int i = 0; i < 4; i++)
#pragma unroll
        for (int j = 0; j < 4; j++) {
            int c = col0 + j;
            g_proj[(size_t)(row0 + i) * H + c] = __fadd_rn(acc[i][j], b_ih[c]);
        }
}

// ============================================================================
// h = xla_tanh(((proj + xW) + b_hh)) + noise   (noise RNG fused in epilogue)
// ============================================================================
__global__ void __launch_bounds__(256, 2)
h_kernel(const float* __restrict__ W_hh, const float* __restrict__ b_hh, int t) {
    extern __shared__ float smem[];
    unsigned long long accp[4][2] = {};
    gemm_core<true>(g_x, W_hh, H, smem, accp);
    float acc[4][4]; unpack_acc(accp, acc);
    int tx = threadIdx.x & 15, ty = threadIdx.x >> 4;
    int row0 = blockIdx.x * 64 + ty * 4;
    int col0 = blockIdx.y * 64 + tx * 4;
    unsigned k0 = g_keybits[4*t];      // split key index 2t
    unsigned k1 = g_keybits[4*t + 1];
#pragma unroll
    for (int i = 0; i < 4; i++) {
        int m = row0 + i;
        int b = m >> 6;
#pragma unroll
        for (int j = 0; j < 4; j++) {
            int c = col0 + j;
            size_t idx = (size_t)m * H + c;
            float pre = __fadd_rn(__fadd_rn(g_proj[((size_t)t * BS + b) * H + c],
                                            acc[i][j]), b_hh[c]);
            unsigned bits = jax_random_bits32(k0, k1, (unsigned)idx);
            float nz = __fmul_rn(jax_normal_from_bits(bits), g_sxstd[c]);
            g_h[idx] = __fadd_rn(xla_tanh(pre), nz);
        }
    }
}

// ============================================================================
// act = relu(h @ W1 + b1)
// ============================================================================
__global__ void __launch_bounds__(256, 2)
ffn_kernel(const float* __restrict__ W1, const float* __restrict__ b1) {
    extern __shared__ float smem[];
    unsigned long long accp[4][2] = {};
    gemm_core<false>(g_h, W1, H, smem, accp);
    float acc[4][4]; unpack_acc(accp, acc);
    int tx = threadIdx.x & 15, ty = threadIdx.x >> 4;
    int row0 = blockIdx.x * 64 + ty * 4;
    int col0 = blockIdx.y * 64 + tx * 4;
#pragma unroll
    for (int i = 0; i < 4; i++)
#pragma unroll
        for (int j = 0; j < 4; j++) {
            int c = col0 + j;
            g_act[(size_t)(row0 + i) * H + c] =
                fmaxf(__fadd_rn(acc[i][j], b1[c]), 0.0f);
        }
}

// ============================================================================
// Fused: y_hat -> out[t]; lp (XLA row-reduce order); log_softmax;
// gumbel argmax; resample gather. One block per batch.
// ============================================================================
__global__ void __launch_bounds__(256, 2)
outres_kernel(const float* __restrict__ W2, const float* __restrict__ b2,
              const float* __restrict__ y, const float* __restrict__ sy,
              float* __restrict__ out, int t) {
    extern __shared__ float smem[];
    __shared__ float lp_s[NP];
    __shared__ float logw_s[NP];
    __shared__ int   I_s[NP];
    __shared__ float red_s[2];

    unsigned long long accp[4][2] = {};
    gemm_core<false>(g_act, W2, OUTD, smem, accp);
    float acc[4][4]; unpack_acc(accp, acc);

    int tid = threadIdx.x;
    int tx = tid & 15, ty = tid >> 4;
    int b = blockIdx.x;                // batch == row block
    int row0 = b * 64 + ty * 4;
    int col0 = tx * 4;

    // stage q[n][c] = d*d/sy (the lp summands) into smem (overwrites GEMM smem;
    // safe: gemm_core ends with __syncthreads)
    float* q_s = smem;                 // [64][65]
#pragma unroll
    for (int i = 0; i < 4; i++) {
        int m = row0 + i;
        int n = ty * 4 + i;
#pragma unroll
        for (int j = 0; j < 4; j++) {
            int c = col0 + j;
            float v = __fadd_rn(acc[i][j], b2[c]);
            out[(((size_t)t * M_ROWS) + m) * OUTD + c] = v;
            float d = __fsub_rn(v, y[(((size_t)t * BS) + b) * OUTD + c]);
            q_s[n * 65 + c] = __fdiv_rn(__fmul_rn(d, d), sy[c]);
        }
    }
    __syncthreads();

    // lp[n] = -0.5*sum_c q - logdet, XLA row-reduce order:
    // lane partial = q[l] + q[l+32], then shfl-down tree 16..1
    int warp = tid >> 5, lane = tid & 31;
    float L = g_logdet;
#pragma unroll
    for (int k = 0; k < 8; k++) {
        int n = warp * 8 + k;
        float s = __fadd_rn(q_s[n * 65 + lane], q_s[n * 65 + lane + 32]);
#pragma unroll
        for (int off = 16; off; off >>= 1)
            s = __fadd_rn(s, __shfl_down_sync(0xffffffffu, s, off));
        if (lane == 0) lp_s[n] = __fsub_rn(-0.5f * s, L);
    }
    __syncthreads();

    // log_softmax: max (exact), then sum(exp(shifted)) with same reduce order
    if (warp == 0) {
        float m1 = fmaxf(lp_s[lane], lp_s[lane + 32]);
#pragma unroll
        for (int off = 16; off; off >>= 1)
            m1 = fmaxf(m1, __shfl_down_sync(0xffffffffu, m1, off));
        m1 = __shfl_sync(0xffffffffu, m1, 0);
        float e1 = expf(__fsub_rn(lp_s[lane], m1));
        float e2 = expf(__fsub_rn(lp_s[lane + 32], m1));
        float s = __fadd_rn(e1, e2);
#pragma unroll
        for (int off = 16; off; off >>= 1)
            s = __fadd_rn(s, __shfl_down_sync(0xffffffffu, s, off));
        if (lane == 0) { red_s[0] = m1; red_s[1] = logf(s); }
    }
    __syncthreads();
    if (tid < NP)
        logw_s[tid] = __fsub_rn(__fsub_rn(lp_s[tid], red_s[0]), red_s[1]);
    __syncthreads();

    // gumbel + logw (reuses smem; prior q reads are behind two syncs)
    float* v_s = smem;                 // [NP][NP]
    unsigned ck0 = g_keybits[4*t + 2];
    unsigned ck1 = g_keybits[4*t + 3];
    for (int l = tid; l < NP * NP; l += 256) {
        int r = l >> 6;
        int n = l & 63;
        unsigned p = (unsigned)(4096 * r + 64 * b + n);
        unsigned bits = jax_random_bits32(ck0, ck1, p);
        v_s[r * 64 + n] = __fadd_rn(jax_gumbel_from_bits(bits), logw_s[n]);
    }
    __syncthreads();

    for (int r = warp; r < NP; r += 8) {
        float v1 = v_s[r * 64 + lane];
        float v2 = v_s[r * 64 + 32 + lane];
        float val; int idx;
        if (v2 > v1) { val = v2; idx = lane + 32; }
        else         { val = v1; idx = lane; }
#pragma unroll
        for (int off = 16; off; off >>= 1) {
            float ov = __shfl_down_sync(0xffffffffu, val, off);
            int   oi = __shfl_down_sync(0xffffffffu, idx, off);
            if (ov > val || (ov == val && oi < idx)) { val = ov; idx = oi; }
        }
        if (lane == 0) I_s[r] = idx;   // first occurrence on tie
    }
    __syncthreads();

    const float4* hsrc = (const float4*)g_h;
    float4*       xdst = (float4*)g_x;
#pragma unroll
    for (int j = 0; j < 16; j++) {
        int lin = tid + 256 * j;       // 0..4095
        int r = lin >> 6;
        int c = lin & 63;
        int src = I_s[r];
        xdst[((size_t)(b * NP + r)) * 64 + c] =
            hsrc[((size_t)(b * NP + src)) * 64 + c];
    }
}

// ============================================================================
// Launch
// ============================================================================
extern "C" void kernel_launch(void* const* d_in, const int* in_sizes, int n_in,
                              void* d_out, int out_size) {
    const float* u    = (const float*)d_in[0];
    const float* y    = (const float*)d_in[1];
    const float* W_ih = (const float*)d_in[2];
    const float* W_hh = (const float*)d_in[3];
    const float* b_ih = (const float*)d_in[4];
    const float* b_hh = (const float*)d_in[5];
    const float* W1   = (const float*)d_in[6];
    const float* b1   = (const float*)d_in[7];
    const float* W2   = (const float*)d_in[8];
    const float* b2   = (const float*)d_in[9];
    const float* sx   = (const float*)d_in[10];
    const float* sy   = (const float*)d_in[11];
    float* out = (float*)d_out;
    (void)in_sizes; (void)n_in; (void)out_size;

    cudaFuncSetAttribute(proj_kernel,   cudaFuncAttributeMaxDynamicSharedMemorySize, SMEM_BYTES);
    cudaFuncSetAttribute(h_kernel,      cudaFuncAttributeMaxDynamicSharedMemorySize, SMEM_BYTES);
    cudaFuncSetAttribute(ffn_kernel,    cudaFuncAttributeMaxDynamicSharedMemorySize, SMEM_BYTES);
    cudaFuncSetAttribute(outres_kernel, cudaFuncAttributeMaxDynamicSharedMemorySize, SMEM_BYTES);

    prep_kernel<<<1, 256>>>(sx, sy);
    x0_kernel<<<STATE_ELEMS / 256, 256>>>();
    proj_kernel<<<dim3(T_STEPS * BS / 64, H / 64), 256, SMEM_BYTES>>>(u, W_ih, b_ih);

    for (int t = 0; t < T_STEPS; t++) {
        h_kernel<<<dim3(M_ROWS / 64, H / 64), 256, SMEM_BYTES>>>(W_hh, b_hh, t);
        ffn_kernel<<<dim3(M_ROWS / 64, H / 64), 256, SMEM_BYTES>>>(W1, b1);
        outres_kernel<<<BS, 256, SMEM_BYTES>>>(W2, b2, y, sy, out, t);
    }
}

// round 8
// speedup vs baseline: 1.1344x; 1.1344x over previous
#include <cuda_runtime.h>
#include <cuda_bf16.h>

// ============================================================================
// Problem constants
// ============================================================================
#define T_STEPS 128
#define BS      64
#define NP      64      // particles
#define H       256
#define OUTD    64
#define M_ROWS  (BS*NP)             // 4096 rows per state GEMM
#define STATE_ELEMS (BS*NP*H)       // 1048576

// Old (R5) smem layout for proj/outres kernels
#define BS_FLOATS   (256*68)        // 17408
#define AS2_FLOATS  (2*16*132)      // 4224
#define SMEM_BYTES  ((BS_FLOATS + AS2_FLOATS)*4)  // 86528

// 64x128-tile GEMM smem: Bs[2][16][132] + As[2][16][68]
#define NBS  (2*16*132)             // 4224
#define NAS  (2*16*68)              // 2176
#define SMEM2_BYTES ((NBS + NAS)*4) // 25600

// ============================================================================
// Device scratch
// ============================================================================
__device__ float g_x[STATE_ELEMS];        // particle state x  [BS*NP, H]
__device__ float g_h[STATE_ELEMS];        // h (post tanh+noise)
__device__ float g_act[STATE_ELEMS];      // FFN hidden activation
__device__ float g_proj[T_STEPS*BS*H];    // u @ W_ih^T + b_ih for all t
__device__ float g_sxstd[H];              // sqrt(sigma_x_diag)
__device__ float g_logdet;                // 0.5*sum(log sy) + 0.5*OUT*log2pi
__device__ unsigned g_keybits[512];       // split-foldlike keys
__device__ unsigned g_x0key[2];           // fold_in(key, 0)

// ============================================================================
// JAX Threefry-2x32 (partitionable mode)
// ============================================================================
__device__ __forceinline__ unsigned rotl32(unsigned v, int d) {
    return __funnelshift_l(v, v, d);
}

__device__ __forceinline__ void threefry2x32(unsigned k0, unsigned k1,
                                             unsigned x, unsigned y,
                                             unsigned &o0, unsigned &o1) {
    unsigned k2 = k0 ^ k1 ^ 0x1BD11BDAu;
    x += k0; y += k1;
#define TF_R(r) { x += y; y = rotl32(y, (r)); y ^= x; }
    TF_R(13) TF_R(15) TF_R(26) TF_R(6)
    x += k1; y += k2 + 1u;
    TF_R(17) TF_R(29) TF_R(16) TF_R(24)
    x += k2; y += k0 + 2u;
    TF_R(13) TF_R(15) TF_R(26) TF_R(6)
    x += k0; y += k1 + 3u;
    TF_R(17) TF_R(29) TF_R(16) TF_R(24)
    x += k1; y += k2 + 4u;
    TF_R(13) TF_R(15) TF_R(26) TF_R(6)
    x += k2; y += k0 + 5u;
#undef TF_R
    o0 = x; o1 = y;
}

__device__ __forceinline__ unsigned jax_random_bits32(unsigned k0, unsigned k1,
                                                      unsigned i) {
    unsigned a, b;
    threefry2x32(k0, k1, 0u, i, a, b);
    return a ^ b;
}

// ============================================================================
// XLA-exact elementwise ops
// ============================================================================
__device__ __forceinline__ float bits_to_unit(unsigned b) {
    return __fsub_rn(__uint_as_float((b >> 9) | 0x3f800000u), 1.0f);
}

__device__ __forceinline__ float erfinv_xla(float x) {
    float w = -logf(__fmul_rn(__fsub_rn(1.0f, x), __fadd_rn(1.0f, x)));
    float p;
    if (w < 5.0f) {
        w = __fsub_rn(w, 2.5f);
        p = 2.81022636e-08f;
        p = __fadd_rn(3.43273939e-07f,  __fmul_rn(p, w));
        p = __fadd_rn(-3.5233877e-06f,  __fmul_rn(p, w));
        p = __fadd_rn(-4.39150654e-06f, __fmul_rn(p, w));
        p = __fadd_rn(0.00021858087f,   __fmul_rn(p, w));
        p = __fadd_rn(-0.00125372503f,  __fmul_rn(p, w));
        p = __fadd_rn(-0.00417768164f,  __fmul_rn(p, w));
        p = __fadd_rn(0.246640727f,     __fmul_rn(p, w));
        p = __fadd_rn(1.50140941f,      __fmul_rn(p, w));
    } else {
        w = __fsub_rn(sqrtf(w), 3.0f);
        p = -0.000200214257f;
        p = __fadd_rn(0.000100950558f,  __fmul_rn(p, w));
        p = __fadd_rn(0.00134934322f,   __fmul_rn(p, w));
        p = __fadd_rn(-0.00367342844f,  __fmul_rn(p, w));
        p = __fadd_rn(0.00573950773f,   __fmul_rn(p, w));
        p = __fadd_rn(-0.0076224613f,   __fmul_rn(p, w));
        p = __fadd_rn(0.00943887047f,   __fmul_rn(p, w));
        p = __fadd_rn(1.00167406f,      __fmul_rn(p, w));
        p = __fadd_rn(2.83297682f,      __fmul_rn(p, w));
    }
    return __fmul_rn(p, x);
}

__device__ __forceinline__ float jax_normal_from_bits(unsigned b) {
    float f = bits_to_unit(b);
    float u = __fadd_rn(__fmul_rn(f, 2.0f), -0.99999994f);
    u = fmaxf(u, -0.99999994f);
    return __fmul_rn(1.41421354f, erfinv_xla(u));
}

__device__ __forceinline__ float jax_gumbel_from_bits(unsigned b) {
    float f = bits_to_unit(b);
    float u = fmaxf(1.17549435e-38f, __fadd_rn(f, 1.17549435e-38f));
    return -logf(-logf(u));
}

__device__ __forceinline__ float xla_tanh(float x) {
    float ax = fabsf(x);
    float xc = fminf(fmaxf(x, -9.0f), 9.0f);
    float x2 = __fmul_rn(xc, xc);
    float p = -2.76076847742355e-16f;
    p = __fadd_rn(2.00018790482477e-13f, __fmul_rn(p, x2));
    p = __fadd_rn(-8.60467152213735e-11f, __fmul_rn(p, x2));
    p = __fadd_rn(5.12229709037114e-08f,  __fmul_rn(p, x2));
    p = __fadd_rn(1.48572235717979e-05f,  __fmul_rn(p, x2));
    p = __fadd_rn(6.37261928875436e-04f,  __fmul_rn(p, x2));
    p = __fadd_rn(4.89352455891786e-03f,  __fmul_rn(p, x2));
    float num = __fmul_rn(xc, p);
    float q = 1.19825839466702e-06f;
    q = __fadd_rn(1.18534705686654e-04f, __fmul_rn(q, x2));
    q = __fadd_rn(2.26843463243900e-03f, __fmul_rn(q, x2));
    q = __fadd_rn(4.89352518554385e-03f, __fmul_rn(q, x2));
    float r = __fdiv_rn(num, q);
    return (ax < 0.0004f) ? x : r;
}

// ============================================================================
// Packed fp32x2 helpers
// ============================================================================
__device__ __forceinline__ void fma2(unsigned long long &d,
                                     unsigned long long a,
                                     unsigned long long b) {
    asm("fma.rn.f32x2 %0, %1, %2, %0;" : "+l"(d) : "l"(a), "l"(b));
}
__device__ __forceinline__ void unpack2(unsigned long long v, float &lo, float &hi) {
    asm("mov.b64 {%0, %1}, %2;" : "=f"(lo), "=f"(hi) : "l"(v));
}
__device__ __forceinline__ unsigned long long dup2(float v) {
    unsigned long long r;
    asm("mov.b64 %0, {%1, %1};" : "=l"(r) : "f"(v));
    return r;
}

// ============================================================================
// Key / scale / logdet preparation
// ============================================================================
__global__ void prep_kernel(const float* __restrict__ sx,
                            const float* __restrict__ sy) {
    int i = threadIdx.x;   // 256 threads
    if (i < H) g_sxstd[i] = sqrtf(sx[i]);
    unsigned sb0, sb1;
    threefry2x32(0u, 42u, 0u, 1u, sb0, sb1);
    unsigned o0, o1;
    threefry2x32(sb0, sb1, 0u, (unsigned)i, o0, o1);
    g_keybits[2*i]     = o0;
    g_keybits[2*i + 1] = o1;
    if (i == 0) {
        unsigned a, b;
        threefry2x32(0u, 42u, 0u, 0u, a, b);
        g_x0key[0] = a; g_x0key[1] = b;
    }
    if (i < 32) {
        float s = __fadd_rn(logf(sy[i]), logf(sy[i + 32]));
#pragma unroll
        for (int off = 16; off; off >>= 1)
            s = __fadd_rn(s, __shfl_down_sync(0xffffffffu, s, off));
        if (i == 0) {
            float t2 = __fmul_rn(32.0f, 1.8378770351409912f);
            g_logdet = __fadd_rn(__fmul_rn(0.5f, s), t2);
        }
    }
}

__global__ void x0_kernel() {
    int i = blockIdx.x * blockDim.x + threadIdx.x;     // < 1048576
    unsigned bits = jax_random_bits32(g_x0key[0], g_x0key[1], (unsigned)i);
    g_x[i] = jax_normal_from_bits(bits);
}

// ============================================================================
// 64x128-tile GEMM core (h / ffn): 256 threads, thread tile 4 rows x
// (4 + 4) cols split at +64 for conflict-free LDS. A scalar in smem
// (broadcast reads), duplicated to f32x2 in registers. B double-buffered
// 16-k chunks. Ascending-k serial fmaf per element (bit-identical chains).
// BT = true : B is [N,256] row-major (C = A * B^T)
// BT = false: B is [256,N] row-major (C = A * B), leading dim ldb
// ============================================================================
template<bool BT>
__device__ __forceinline__ void gemm_64x128(const float* __restrict__ A,
                                            const float* __restrict__ B,
                                            int ldb, float* smem,
                                            unsigned long long acc[4][4]) {
    float* Bs = smem;              // [2][16][132]
    float* As = smem + NBS;        // [2][16][68]
    int tid = threadIdx.x;
    int tx = tid & 15, ty = tid >> 4;

    int arow = tid >> 2;           // 0..63
    int akq  = (tid & 3) << 2;     // 0,4,8,12
    const float* Ap = A + (size_t)(blockIdx.x*64 + arow)*256 + akq;

    // B load mapping (two float4 per thread per chunk)
    int bn0 = blockIdx.y * 128;
    int bnA = 0, bkA = 0, bnB = 0, bkB = 0;
    const float *BpA, *BpB;
    if (BT) {
        bnA = tid >> 2;          bkA = (tid & 3) << 2;
        bnB = (tid + 256) >> 2;  bkB = (tid & 3) << 2;
        BpA = B + (size_t)(bn0 + bnA)*256 + bkA;
        BpB = B + (size_t)(bn0 + bnB)*256 + bkB;
    } else {
        bkA = tid >> 5;          bnA = (tid & 31) << 2;
        bkB = (tid + 256) >> 5;  bnB = (tid & 31) << 2;
        BpA = B + (size_t)bkA*ldb + bn0 + bnA;
        BpB = B + (size_t)bkB*ldb + bn0 + bnB;
    }

    // prologue: chunk 0 into buf 0
    {
        float4 av = *(const float4*)(Ap);
        float4 b0 = *(const float4*)(BpA);
        float4 b1 = *(const float4*)(BpB);
        float* Asd = As;
        Asd[(akq+0)*68 + arow] = av.x; Asd[(akq+1)*68 + arow] = av.y;
        Asd[(akq+2)*68 + arow] = av.z; Asd[(akq+3)*68 + arow] = av.w;
        float* Bsd = Bs;
        if (BT) {
            Bsd[(bkA+0)*132 + bnA] = b0.x; Bsd[(bkA+1)*132 + bnA] = b0.y;
            Bsd[(bkA+2)*132 + bnA] = b0.z; Bsd[(bkA+3)*132 + bnA] = b0.w;
            Bsd[(bkB+0)*132 + bnB] = b1.x; Bsd[(bkB+1)*132 + bnB] = b1.y;
            Bsd[(bkB+2)*132 + bnB] = b1.z; Bsd[(bkB+3)*132 + bnB] = b1.w;
        } else {
            *(float4*)&Bsd[bkA*132 + bnA] = b0;
            *(float4*)&Bsd[bkB*132 + bnB] = b1;
        }
    }
    __syncthreads();

    for (int c = 0; c < 16; c++) {
        float4 av, b0, b1;
        if (c + 1 < 16) {
            av = *(const float4*)(Ap + (c+1)*16);
            if (BT) {
                b0 = *(const float4*)(BpA + (c+1)*16);
                b1 = *(const float4*)(BpB + (c+1)*16);
            } else {
                b0 = *(const float4*)(BpA + (size_t)(c+1)*16*ldb);
                b1 = *(const float4*)(BpB + (size_t)(c+1)*16*ldb);
            }
        }
        const float* Asb = As + (c & 1) * (16*68);
        const float* Bsb = Bs + (c & 1) * (16*132);
#pragma unroll
        for (int k = 0; k < 16; k++) {
            float4 a = *(const float4*)&Asb[k*68 + ty*4];
            ulonglong2 p0 = *(const ulonglong2*)&Bsb[k*132 + tx*4];
            ulonglong2 p1 = *(const ulonglong2*)&Bsb[k*132 + 64 + tx*4];
            unsigned long long a0 = dup2(a.x), a1 = dup2(a.y);
            unsigned long long a2 = dup2(a.z), a3 = dup2(a.w);
            fma2(acc[0][0], a0, p0.x); fma2(acc[0][1], a0, p0.y);
            fma2(acc[0][2], a0, p1.x); fma2(acc[0][3], a0, p1.y);
            fma2(acc[1][0], a1, p0.x); fma2(acc[1][1], a1, p0.y);
            fma2(acc[1][2], a1, p1.x); fma2(acc[1][3], a1, p1.y);
            fma2(acc[2][0], a2, p0.x); fma2(acc[2][1], a2, p0.y);
            fma2(acc[2][2], a2, p1.x); fma2(acc[2][3], a2, p1.y);
            fma2(acc[3][0], a3, p0.x); fma2(acc[3][1], a3, p0.y);
            fma2(acc[3][2], a3, p1.x); fma2(acc[3][3], a3, p1.y);
        }
        if (c + 1 < 16) {
            float* Asd = As + ((c+1) & 1) * (16*68);
            Asd[(akq+0)*68 + arow] = av.x; Asd[(akq+1)*68 + arow] = av.y;
            Asd[(akq+2)*68 + arow] = av.z; Asd[(akq+3)*68 + arow] = av.w;
            float* Bsd = Bs + ((c+1) & 1) * (16*132);
            if (BT) {
                Bsd[(bkA+0)*132 + bnA] = b0.x; Bsd[(bkA+1)*132 + bnA] = b0.y;
                Bsd[(bkA+2)*132 + bnA] = b0.z; Bsd[(bkA+3)*132 + bnA] = b0.w;
                Bsd[(bkB+0)*132 + bnB] = b1.x; Bsd[(bkB+1)*132 + bnB] = b1.y;
                Bsd[(bkB+2)*132 + bnB] = b1.z; Bsd[(bkB+3)*132 + bnB] = b1.w;
            } else {
                *(float4*)&Bsd[bkA*132 + bnA] = b0;
                *(float4*)&Bsd[bkB*132 + bnB] = b1;
            }
        }
        __syncthreads();
    }
}

// Column of accumulator slot (i, p, e): cols tx*4 block p<2, +64 block p>=2
__device__ __forceinline__ int acc_col(int tx, int p, int e) {
    return (p < 2) ? (tx*4 + 2*p + e) : (64 + tx*4 + 2*(p-2) + e);
}

// ============================================================================
// h = xla_tanh((proj + xW) + b_hh) + noise   (64x128 tile, fused RNG)
// ============================================================================
__global__ void __launch_bounds__(256, 2)
h_kernel(const float* __restrict__ W_hh, const float* __restrict__ b_hh, int t) {
    extern __shared__ float smem[];
    unsigned long long acc[4][4] = {};
    gemm_64x128<true>(g_x, W_hh, H, smem, acc);
    int tx = threadIdx.x & 15, ty = threadIdx.x >> 4;
    int row0 = blockIdx.x * 64 + ty * 4;
    int cb = blockIdx.y * 128;
    unsigned k0 = g_keybits[4*t];
    unsigned k1 = g_keybits[4*t + 1];
#pragma unroll
    for (int i = 0; i < 4; i++) {
        int m = row0 + i;
        int b = m >> 6;
        const float* projrow = g_proj + ((size_t)t * BS + b) * H;
#pragma unroll
        for (int p = 0; p < 4; p++) {
            float v[2];
            unpack2(acc[i][p], v[0], v[1]);
#pragma unroll
            for (int e = 0; e < 2; e++) {
                int c = cb + acc_col(tx, p, e);
                size_t idx = (size_t)m * H + c;
                float pre = __fadd_rn(__fadd_rn(projrow[c], v[e]), b_hh[c]);
                unsigned bits = jax_random_bits32(k0, k1, (unsigned)idx);
                float nz = __fmul_rn(jax_normal_from_bits(bits), g_sxstd[c]);
                g_h[idx] = __fadd_rn(xla_tanh(pre), nz);
            }
        }
    }
}

// ============================================================================
// act = relu(h @ W1 + b1)   (64x128 tile)
// ============================================================================
__global__ void __launch_bounds__(256, 2)
ffn_kernel(const float* __restrict__ W1, const float* __restrict__ b1) {
    extern __shared__ float smem[];
    unsigned long long acc[4][4] = {};
    gemm_64x128<false>(g_h, W1, H, smem, acc);
    int tx = threadIdx.x & 15, ty = threadIdx.x >> 4;
    int row0 = blockIdx.x * 64 + ty * 4;
    int cb = blockIdx.y * 128;
#pragma unroll
    for (int i = 0; i < 4; i++) {
        int m = row0 + i;
#pragma unroll
        for (int p = 0; p < 4; p++) {
            float v[2];
            unpack2(acc[i][p], v[0], v[1]);
#pragma unroll
            for (int e = 0; e < 2; e++) {
                int c = cb + acc_col(tx, p, e);
                g_act[(size_t)m * H + c] = fmaxf(__fadd_rn(v[e], b1[c]), 0.0f);
            }
        }
    }
}

// ============================================================================
// OLD (R5) GEMM core — used by proj (runs once) and outres (N=64)
// ============================================================================
template<bool BT>
__device__ __forceinline__ void gemm_core(const float* __restrict__ A,
                                          const float* __restrict__ B,
                                          int ldb, float* smem,
                                          unsigned long long accp[4][2]) {
    float* Bsm = smem;                 // [256][68]
    float* As2 = smem + BS_FLOATS;     // [2][16][132]
    int tid = threadIdx.x;

    if (BT) {
#pragma unroll
        for (int it = 0; it < 16; it++) {
            int l = tid + 256 * it;
            int n = l & 63;
            int kq = (l >> 6) << 2;
            float4 v = *(const float4*)(B + (size_t)(blockIdx.y*64 + n)*256 + kq);
            Bsm[(kq+0)*68 + n] = v.x; Bsm[(kq+1)*68 + n] = v.y;
            Bsm[(kq+2)*68 + n] = v.z; Bsm[(kq+3)*68 + n] = v.w;
        }
    } else {
#pragma unroll
        for (int it = 0; it < 16; it++) {
            int l = tid + 256 * it;
            int k = l >> 4;
            int nq = (l & 15) << 2;
            float4 v = *(const float4*)(B + (size_t)k*ldb + blockIdx.y*64 + nq);
            *(float4*)&Bsm[k*68 + nq] = v;
        }
    }

    int arow = tid >> 2;
    int akq  = (tid & 3) << 2;
    const float* Ap = A + (size_t)(blockIdx.x*64 + arow)*256 + akq;
    int ty = tid >> 4, tx = tid & 15;

    {
        float4 av = *(const float4*)(Ap);
        float* d = As2;
        *(float2*)&d[(akq+0)*132 + arow*2] = make_float2(av.x, av.x);
        *(float2*)&d[(akq+1)*132 + arow*2] = make_float2(av.y, av.y);
        *(float2*)&d[(akq+2)*132 + arow*2] = make_float2(av.z, av.z);
        *(float2*)&d[(akq+3)*132 + arow*2] = make_float2(av.w, av.w);
    }
    __syncthreads();

    for (int c = 0; c < 16; c++) {
        float4 nv;
        if (c + 1 < 16) nv = *(const float4*)(Ap + (c+1)*16);
        const float* As = As2 + (c & 1) * (16*132);
        const float* Bc = Bsm + c * 16 * 68;
#pragma unroll
        for (int k = 0; k < 16; k++) {
            ulonglong2 bp  = *(const ulonglong2*)&Bc[k*68 + tx*4];
            ulonglong2 ad0 = *(const ulonglong2*)&As[k*132 + ty*8];
            ulonglong2 ad1 = *(const ulonglong2*)&As[k*132 + ty*8 + 4];
            fma2(accp[0][0], ad0.x, bp.x); fma2(accp[0][1], ad0.x, bp.y);
            fma2(accp[1][0], ad0.y, bp.x); fma2(accp[1][1], ad0.y, bp.y);
            fma2(accp[2][0], ad1.x, bp.x); fma2(accp[2][1], ad1.x, bp.y);
            fma2(accp[3][0], ad1.y, bp.x); fma2(accp[3][1], ad1.y, bp.y);
        }
        if (c + 1 < 16) {
            float* d = As2 + ((c+1) & 1) * (16*132);
            *(float2*)&d[(akq+0)*132 + arow*2] = make_float2(nv.x, nv.x);
            *(float2*)&d[(akq+1)*132 + arow*2] = make_float2(nv.y, nv.y);
            *(float2*)&d[(akq+2)*132 + arow*2] = make_float2(nv.z, nv.z);
            *(float2*)&d[(akq+3)*132 + arow*2] = make_float2(nv.w, nv.w);
        }
        __syncthreads();
    }
}

__device__ __forceinline__ void unpack_acc(unsigned long long accp[4][2],
                                           float acc[4][4]) {
#pragma unroll
    for (int i = 0; i < 4; i++) {
        unpack2(accp[i][0], acc[i][0], acc[i][1]);
        unpack2(accp[i][1], acc[i][2], acc[i][3]);
    }
}

// ============================================================================
// proj[t,b,:] = u[t,b,:] @ W_ih^T + b_ih  (runs once)
// ============================================================================
__global__ void __launch_bounds__(256, 2)
proj_kernel(const float* __restrict__ u, const float* __restrict__ W_ih,
            const float* __restrict__ b_ih) {
    extern __shared__ float smem[];
    unsigned long long accp[4][2] = {};
    gemm_core<true>(u, W_ih, H, smem, accp);
    float acc[4][4]; unpack_acc(accp, acc);
    int tx = threadIdx.x & 15, ty = threadIdx.x >> 4;
    int row0 = blockIdx.x * 64 + ty * 4;
    int col0 = blockIdx.y * 64 + tx * 4;
#pragma unroll
    for (int i = 0; i < 4; i++)
#pragma unroll
        for (int j = 0; j < 4; j++) {
            int c = col0 + j;
            g_proj[(size_t)(row0 + i) * H + c] = __fadd_rn(acc[i][j], b_ih[c]);
        }
}

// ============================================================================
// Fused: y_hat -> out[t]; lp; log_softmax; gumbel argmax; resample gather.
// ============================================================================
__global__ void __launch_bounds__(256, 2)
outres_kernel(const float* __restrict__ W2, const float* __restrict__ b2,
              const float* __restrict__ y, const float* __restrict__ sy,
              float* __restrict__ out, int t) {
    extern __shared__ float smem[];
    __shared__ float lp_s[NP];
    __shared__ float logw_s[NP];
    __shared__ int   I_s[NP];
    __shared__ float red_s[2];

    unsigned long long accp[4][2] = {};
    gemm_core<false>(g_act, W2, OUTD, smem, accp);
    float acc[4][4]; unpack_acc(accp, acc);

    int tid = threadIdx.x;
    int tx = tid & 15, ty = tid >> 4;
    int b = blockIdx.x;
    int row0 = b * 64 + ty * 4;
    int col0 = tx * 4;

    float* q_s = smem;                 // [64][65]
#pragma unroll
    for (int i = 0; i < 4; i++) {
        int m = row0 + i;
        int n = ty * 4 + i;
#pragma unroll
        for (int j = 0; j < 4; j++) {
            int c = col0 + j;
            float v = __fadd_rn(acc[i][j], b2[c]);
            out[(((size_t)t * M_ROWS) + m) * OUTD + c] = v;
            float d = __fsub_rn(v, y[(((size_t)t * BS) + b) * OUTD + c]);
            q_s[n * 65 + c] = __fdiv_rn(__fmul_rn(d, d), sy[c]);
        }
    }
    __syncthreads();

    int warp = tid >> 5, lane = tid & 31;
    float L = g_logdet;
#pragma unroll
    for (int k = 0; k < 8; k++) {
        int n = warp * 8 + k;
        float s = __fadd_rn(q_s[n * 65 + lane], q_s[n * 65 + lane + 32]);
#pragma unroll
        for (int off = 16; off; off >>= 1)
            s = __fadd_rn(s, __shfl_down_sync(0xffffffffu, s, off));
        if (lane == 0) lp_s[n] = __fsub_rn(-0.5f * s, L);
    }
    __syncthreads();

    if (warp == 0) {
        float m1 = fmaxf(lp_s[lane], lp_s[lane + 32]);
#pragma unroll
        for (int off = 16; off; off >>= 1)
            m1 = fmaxf(m1, __shfl_down_sync(0xffffffffu, m1, off));
        m1 = __shfl_sync(0xffffffffu, m1, 0);
        float e1 = expf(__fsub_rn(lp_s[lane], m1));
        float e2 = expf(__fsub_rn(lp_s[lane + 32], m1));
        float s = __fadd_rn(e1, e2);
#pragma unroll
        for (int off = 16; off; off >>= 1)
            s = __fadd_rn(s, __shfl_down_sync(0xffffffffu, s, off));
        if (lane == 0) { red_s[0] = m1; red_s[1] = logf(s); }
    }
    __syncthreads();
    if (tid < NP)
        logw_s[tid] = __fsub_rn(__fsub_rn(lp_s[tid], red_s[0]), red_s[1]);
    __syncthreads();

    float* v_s = smem;                 // [NP][NP]
    unsigned ck0 = g_keybits[4*t + 2];
    unsigned ck1 = g_keybits[4*t + 3];
    for (int l = tid; l < NP * NP; l += 256) {
        int r = l >> 6;
        int n = l & 63;
        unsigned p = (unsigned)(4096 * r + 64 * b + n);
        unsigned bits = jax_random_bits32(ck0, ck1, p);
        v_s[r * 64 + n] = __fadd_rn(jax_gumbel_from_bits(bits), logw_s[n]);
    }
    __syncthreads();

    for (int r = warp; r < NP; r += 8) {
        float v1 = v_s[r * 64 + lane];
        float v2 = v_s[r * 64 + 32 + lane];
        float val; int idx;
        if (v2 > v1) { val = v2; idx = lane + 32; }
        else         { val = v1; idx = lane; }
#pragma unroll
        for (int off = 16; off; off >>= 1) {
            float ov = __shfl_down_sync(0xffffffffu, val, off);
            int   oi = __shfl_down_sync(0xffffffffu, idx, off);
            if (ov > val || (ov == val && oi < idx)) { val = ov; idx = oi; }
        }
        if (lane == 0) I_s[r] = idx;
    }
    __syncthreads();

    const float4* hsrc = (const float4*)g_h;
    float4*       xdst = (float4*)g_x;
#pragma unroll
    for (int j = 0; j < 16; j++) {
        int lin = tid + 256 * j;
        int r = lin >> 6;
        int c = lin & 63;
        int src = I_s[r];
        xdst[((size_t)(b * NP + r)) * 64 + c] =
            hsrc[((size_t)(b * NP + src)) * 64 + c];
    }
}

// ============================================================================
// Launch
// ============================================================================
extern "C" void kernel_launch(void* const* d_in, const int* in_sizes, int n_in,
                              void* d_out, int out_size) {
    const float* u    = (const float*)d_in[0];
    const float* y    = (const float*)d_in[1];
    const float* W_ih = (const float*)d_in[2];
    const float* W_hh = (const float*)d_in[3];
    const float* b_ih = (const float*)d_in[4];
    const float* b_hh = (const float*)d_in[5];
    const float* W1   = (const float*)d_in[6];
    const float* b1   = (const float*)d_in[7];
    const float* W2   = (const float*)d_in[8];
    const float* b2   = (const float*)d_in[9];
    const float* sx   = (const float*)d_in[10];
    const float* sy   = (const float*)d_in[11];
    float* out = (float*)d_out;
    (void)in_sizes; (void)n_in; (void)out_size;

    cudaFuncSetAttribute(proj_kernel,   cudaFuncAttributeMaxDynamicSharedMemorySize, SMEM_BYTES);
    cudaFuncSetAttribute(outres_kernel, cudaFuncAttributeMaxDynamicSharedMemorySize, SMEM_BYTES);
    cudaFuncSetAttribute(h_kernel,      cudaFuncAttributeMaxDynamicSharedMemorySize, SMEM2_BYTES);
    cudaFuncSetAttribute(ffn_kernel,    cudaFuncAttributeMaxDynamicSharedMemorySize, SMEM2_BYTES);

    prep_kernel<<<1, 256>>>(sx, sy);
    x0_kernel<<<STATE_ELEMS / 256, 256>>>();
    proj_kernel<<<dim3(T_STEPS * BS / 64, H / 64), 256, SMEM_BYTES>>>(u, W_ih, b_ih);

    for (int t = 0; t < T_STEPS; t++) {
        h_kernel<<<dim3(M_ROWS / 64, H / 128), 256, SMEM2_BYTES>>>(W_hh, b_hh, t);
        ffn_kernel<<<dim3(M_ROWS / 64, H / 128), 256, SMEM2_BYTES>>>(W1, b1);
        outres_kernel<<<BS, 256, SMEM_BYTES>>>(W2, b2, y, sy, out, t);
    }
}

// round 9
// speedup vs baseline: 1.1503x; 1.0140x over previous
#include <cuda_runtime.h>
#include <cuda_bf16.h>

// ============================================================================
// Problem constants
// ============================================================================
#define T_STEPS 128
#define BS      64
#define NP      64      // particles
#define H       256
#define OUTD    64
#define M_ROWS  (BS*NP)             // 4096 rows per state GEMM
#define STATE_ELEMS (BS*NP*H)       // 1048576

// proj (runs once) keeps the old 64x64 full-B core
#define BS_FLOATS   (256*68)        // 17408
#define AS2_FLOATS  (2*16*132)      // 4224
#define SMEM_BYTES  ((BS_FLOATS + AS2_FLOATS)*4)  // 86528

// h/ffn 32x64-tile core: Bs[2][16][68] + As[2][16][36]
#define HBS  (2*16*68)              // 2176
#define HAS  (2*16*36)              // 1152
#define SMEM_H_BYTES ((HBS + HAS)*4)   // 13312

// outres 64x64-tile core: Bs[2][16][68] + As[2][16][68]
#define OBS  (2*16*68)              // 2176
#define OAS  (2*16*68)              // 2176
#define SMEM_O_BYTES ((OBS + OAS)*4)   // 17408

// ============================================================================
// Device scratch
// ============================================================================
__device__ float g_x[STATE_ELEMS];        // particle state x  [BS*NP, H]
__device__ float g_h[STATE_ELEMS];        // h (post tanh+noise)
__device__ float g_act[STATE_ELEMS];      // FFN hidden activation
__device__ float g_proj[T_STEPS*BS*H];    // u @ W_ih^T + b_ih for all t
__device__ float g_sxstd[H];              // sqrt(sigma_x_diag)
__device__ float g_logdet;                // 0.5*sum(log sy) + 0.5*OUT*log2pi
__device__ unsigned g_keybits[512];       // split-foldlike keys
__device__ unsigned g_x0key[2];           // fold_in(key, 0)

// ============================================================================
// JAX Threefry-2x32 (partitionable mode)
// ============================================================================
__device__ __forceinline__ unsigned rotl32(unsigned v, int d) {
    return __funnelshift_l(v, v, d);
}

__device__ __forceinline__ void threefry2x32(unsigned k0, unsigned k1,
                                             unsigned x, unsigned y,
                                             unsigned &o0, unsigned &o1) {
    unsigned k2 = k0 ^ k1 ^ 0x1BD11BDAu;
    x += k0; y += k1;
#define TF_R(r) { x += y; y = rotl32(y, (r)); y ^= x; }
    TF_R(13) TF_R(15) TF_R(26) TF_R(6)
    x += k1; y += k2 + 1u;
    TF_R(17) TF_R(29) TF_R(16) TF_R(24)
    x += k2; y += k0 + 2u;
    TF_R(13) TF_R(15) TF_R(26) TF_R(6)
    x += k0; y += k1 + 3u;
    TF_R(17) TF_R(29) TF_R(16) TF_R(24)
    x += k1; y += k2 + 4u;
    TF_R(13) TF_R(15) TF_R(26) TF_R(6)
    x += k2; y += k0 + 5u;
#undef TF_R
    o0 = x; o1 = y;
}

__device__ __forceinline__ unsigned jax_random_bits32(unsigned k0, unsigned k1,
                                                      unsigned i) {
    unsigned a, b;
    threefry2x32(k0, k1, 0u, i, a, b);
    return a ^ b;
}

// ============================================================================
// XLA-exact elementwise ops (unchanged from R8 — bit-identical)
// ============================================================================
__device__ __forceinline__ float bits_to_unit(unsigned b) {
    return __fsub_rn(__uint_as_float((b >> 9) | 0x3f800000u), 1.0f);
}

__device__ __forceinline__ float erfinv_xla(float x) {
    float w = -logf(__fmul_rn(__fsub_rn(1.0f, x), __fadd_rn(1.0f, x)));
    float p;
    if (w < 5.0f) {
        w = __fsub_rn(w, 2.5f);
        p = 2.81022636e-08f;
        p = __fadd_rn(3.43273939e-07f,  __fmul_rn(p, w));
        p = __fadd_rn(-3.5233877e-06f,  __fmul_rn(p, w));
        p = __fadd_rn(-4.39150654e-06f, __fmul_rn(p, w));
        p = __fadd_rn(0.00021858087f,   __fmul_rn(p, w));
        p = __fadd_rn(-0.00125372503f,  __fmul_rn(p, w));
        p = __fadd_rn(-0.00417768164f,  __fmul_rn(p, w));
        p = __fadd_rn(0.246640727f,     __fmul_rn(p, w));
        p = __fadd_rn(1.50140941f,      __fmul_rn(p, w));
    } else {
        w = __fsub_rn(sqrtf(w), 3.0f);
        p = -0.000200214257f;
        p = __fadd_rn(0.000100950558f,  __fmul_rn(p, w));
        p = __fadd_rn(0.00134934322f,   __fmul_rn(p, w));
        p = __fadd_rn(-0.00367342844f,  __fmul_rn(p, w));
        p = __fadd_rn(0.00573950773f,   __fmul_rn(p, w));
        p = __fadd_rn(-0.0076224613f,   __fmul_rn(p, w));
        p = __fadd_rn(0.00943887047f,   __fmul_rn(p, w));
        p = __fadd_rn(1.00167406f,      __fmul_rn(p, w));
        p = __fadd_rn(2.83297682f,      __fmul_rn(p, w));
    }
    return __fmul_rn(p, x);
}

__device__ __forceinline__ float jax_normal_from_bits(unsigned b) {
    float f = bits_to_unit(b);
    float u = __fadd_rn(__fmul_rn(f, 2.0f), -0.99999994f);
    u = fmaxf(u, -0.99999994f);
    return __fmul_rn(1.41421354f, erfinv_xla(u));
}

__device__ __forceinline__ float jax_gumbel_from_bits(unsigned b) {
    float f = bits_to_unit(b);
    float u = fmaxf(1.17549435e-38f, __fadd_rn(f, 1.17549435e-38f));
    return -logf(-logf(u));
}

__device__ __forceinline__ float xla_tanh(float x) {
    float ax = fabsf(x);
    float xc = fminf(fmaxf(x, -9.0f), 9.0f);
    float x2 = __fmul_rn(xc, xc);
    float p = -2.76076847742355e-16f;
    p = __fadd_rn(2.00018790482477e-13f, __fmul_rn(p, x2));
    p = __fadd_rn(-8.60467152213735e-11f, __fmul_rn(p, x2));
    p = __fadd_rn(5.12229709037114e-08f,  __fmul_rn(p, x2));
    p = __fadd_rn(1.48572235717979e-05f,  __fmul_rn(p, x2));
    p = __fadd_rn(6.37261928875436e-04f,  __fmul_rn(p, x2));
    p = __fadd_rn(4.89352455891786e-03f,  __fmul_rn(p, x2));
    float num = __fmul_rn(xc, p);
    float q = 1.19825839466702e-06f;
    q = __fadd_rn(1.18534705686654e-04f, __fmul_rn(q, x2));
    q = __fadd_rn(2.26843463243900e-03f, __fmul_rn(q, x2));
    q = __fadd_rn(4.89352518554385e-03f, __fmul_rn(q, x2));
    float r = __fdiv_rn(num, q);
    return (ax < 0.0004f) ? x : r;
}

// ============================================================================
// Packed fp32x2 helpers
// ============================================================================
__device__ __forceinline__ void fma2(unsigned long long &d,
                                     unsigned long long a,
                                     unsigned long long b) {
    asm("fma.rn.f32x2 %0, %1, %2, %0;" : "+l"(d) : "l"(a), "l"(b));
}
__device__ __forceinline__ void unpack2(unsigned long long v, float &lo, float &hi) {
    asm("mov.b64 {%0, %1}, %2;" : "=f"(lo), "=f"(hi) : "l"(v));
}
__device__ __forceinline__ unsigned long long dup2(float v) {
    unsigned long long r;
    asm("mov.b64 %0, {%1, %1};" : "=l"(r) : "f"(v));
    return r;
}

// ============================================================================
// Key / scale / logdet preparation
// ============================================================================
__global__ void prep_kernel(const float* __restrict__ sx,
                            const float* __restrict__ sy) {
    int i = threadIdx.x;   // 256 threads
    if (i < H) g_sxstd[i] = sqrtf(sx[i]);
    unsigned sb0, sb1;
    threefry2x32(0u, 42u, 0u, 1u, sb0, sb1);
    unsigned o0, o1;
    threefry2x32(sb0, sb1, 0u, (unsigned)i, o0, o1);
    g_keybits[2*i]     = o0;
    g_keybits[2*i + 1] = o1;
    if (i == 0) {
        unsigned a, b;
        threefry2x32(0u, 42u, 0u, 0u, a, b);
        g_x0key[0] = a; g_x0key[1] = b;
    }
    if (i < 32) {
        float s = __fadd_rn(logf(sy[i]), logf(sy[i + 32]));
#pragma unroll
        for (int off = 16; off; off >>= 1)
            s = __fadd_rn(s, __shfl_down_sync(0xffffffffu, s, off));
        if (i == 0) {
            float t2 = __fmul_rn(32.0f, 1.8378770351409912f);
            g_logdet = __fadd_rn(__fmul_rn(0.5f, s), t2);
        }
    }
}

__global__ void x0_kernel() {
    int i = blockIdx.x * blockDim.x + threadIdx.x;     // < 1048576
    unsigned bits = jax_random_bits32(g_x0key[0], g_x0key[1], (unsigned)i);
    g_x[i] = jax_normal_from_bits(bits);
}

// ============================================================================
// 32x64-tile GEMM core (h / ffn): 128 threads, thread tile 4 rows x 4 cols
// (2 f32x2 accs per row). A broadcast from smem, B conflict-free.
// grid (M/32, N/64). Ascending-k serial per element (bit-identical).
// BT = true : B is [N,256] row-major (C = A * B^T)
// BT = false: B is [256,N] row-major (C = A * B), leading dim ldb
// ============================================================================
template<bool BT>
__device__ __forceinline__ void gemm_32x64(const float* __restrict__ A,
                                           const float* __restrict__ B,
                                           int ldb, float* smem,
                                           unsigned long long acc[4][2]) {
    float* Bs = smem;              // [2][16][68]
    float* As = smem + HBS;        // [2][16][36]
    int tid = threadIdx.x;         // 0..127
    int tx = tid & 15, ty = tid >> 4;   // tx 0..15, ty 0..7

    // A loader: 128 float4 = 32 rows x 16 k
    int arow = tid >> 2;           // 0..31
    int akq  = (tid & 3) << 2;     // 0,4,8,12
    const float* Ap = A + (size_t)(blockIdx.x*32 + arow)*256 + akq;

    // B loader: 2 float4/thread = 64 x 16
    int bn0 = blockIdx.y * 64;
    int bn_0 = 0, bn_1 = 0, bk_0 = 0, bk_1 = 0;
    const float *Bp0, *Bp1;
    if (BT) {
        bn_0 = tid >> 2;  bn_1 = bn_0 + 32;       // n 0..31, 32..63
        bk_0 = (tid & 3) << 2;  bk_1 = bk_0;      // kq 0,4,8,12
        Bp0 = B + (size_t)(bn0 + bn_0)*256 + bk_0;
        Bp1 = B + (size_t)(bn0 + bn_1)*256 + bk_1;
    } else {
        bk_0 = tid >> 4;  bk_1 = bk_0 + 8;        // k 0..7, 8..15
        bn_0 = (tid & 15) << 2;  bn_1 = bn_0;     // nq 0..60
        Bp0 = B + (size_t)bk_0*ldb + bn0 + bn_0;
        Bp1 = B + (size_t)bk_1*ldb + bn0 + bn_1;
    }

    // prologue: chunk 0 -> buf 0
    {
        float4 av = *(const float4*)(Ap);
        float4 b0 = *(const float4*)(Bp0);
        float4 b1 = *(const float4*)(Bp1);
        float* Asd = As;
        Asd[(akq+0)*36 + arow] = av.x; Asd[(akq+1)*36 + arow] = av.y;
        Asd[(akq+2)*36 + arow] = av.z; Asd[(akq+3)*36 + arow] = av.w;
        float* Bsd = Bs;
        if (BT) {
            Bsd[(bk_0+0)*68 + bn_0] = b0.x; Bsd[(bk_0+1)*68 + bn_0] = b0.y;
            Bsd[(bk_0+2)*68 + bn_0] = b0.z; Bsd[(bk_0+3)*68 + bn_0] = b0.w;
            Bsd[(bk_1+0)*68 + bn_1] = b1.x; Bsd[(bk_1+1)*68 + bn_1] = b1.y;
            Bsd[(bk_1+2)*68 + bn_1] = b1.z; Bsd[(bk_1+3)*68 + bn_1] = b1.w;
        } else {
            *(float4*)&Bsd[bk_0*68 + bn_0] = b0;
            *(float4*)&Bsd[bk_1*68 + bn_1] = b1;
        }
    }
    __syncthreads();

    for (int c = 0; c < 16; c++) {
        float4 av, b0, b1;
        if (c + 1 < 16) {
            av = *(const float4*)(Ap + (c+1)*16);
            if (BT) {
                b0 = *(const float4*)(Bp0 + (c+1)*16);
                b1 = *(const float4*)(Bp1 + (c+1)*16);
            } else {
                b0 = *(const float4*)(Bp0 + (size_t)(c+1)*16*ldb);
                b1 = *(const float4*)(Bp1 + (size_t)(c+1)*16*ldb);
            }
        }
        const float* Asb = As + (c & 1) * (16*36);
        const float* Bsb = Bs + (c & 1) * (16*68);
#pragma unroll
        for (int k = 0; k < 16; k++) {
            float4 a = *(const float4*)&Asb[k*36 + ty*4];
            ulonglong2 bp = *(const ulonglong2*)&Bsb[k*68 + tx*4];
            unsigned long long a0 = dup2(a.x), a1 = dup2(a.y);
            unsigned long long a2 = dup2(a.z), a3 = dup2(a.w);
            fma2(acc[0][0], a0, bp.x); fma2(acc[0][1], a0, bp.y);
            fma2(acc[1][0], a1, bp.x); fma2(acc[1][1], a1, bp.y);
            fma2(acc[2][0], a2, bp.x); fma2(acc[2][1], a2, bp.y);
            fma2(acc[3][0], a3, bp.x); fma2(acc[3][1], a3, bp.y);
        }
        if (c + 1 < 16) {
            float* Asd = As + ((c+1) & 1) * (16*36);
            Asd[(akq+0)*36 + arow] = av.x; Asd[(akq+1)*36 + arow] = av.y;
            Asd[(akq+2)*36 + arow] = av.z; Asd[(akq+3)*36 + arow] = av.w;
            float* Bsd = Bs + ((c+1) & 1) * (16*68);
            if (BT) {
                Bsd[(bk_0+0)*68 + bn_0] = b0.x; Bsd[(bk_0+1)*68 + bn_0] = b0.y;
                Bsd[(bk_0+2)*68 + bn_0] = b0.z; Bsd[(bk_0+3)*68 + bn_0] = b0.w;
                Bsd[(bk_1+0)*68 + bn_1] = b1.x; Bsd[(bk_1+1)*68 + bn_1] = b1.y;
                Bsd[(bk_1+2)*68 + bn_1] = b1.z; Bsd[(bk_1+3)*68 + bn_1] = b1.w;
            } else {
                *(float4*)&Bsd[bk_0*68 + bn_0] = b0;
                *(float4*)&Bsd[bk_1*68 + bn_1] = b1;
            }
        }
        __syncthreads();
    }
}

// ============================================================================
// h = xla_tanh((proj + xW) + b_hh) + noise   (32x64 tile, fused RNG)
// ============================================================================
__global__ void __launch_bounds__(128, 4)
h_kernel(const float* __restrict__ W_hh, const float* __restrict__ b_hh, int t) {
    extern __shared__ float smem[];
    unsigned long long acc[4][2] = {};
    gemm_32x64<true>(g_x, W_hh, H, smem, acc);
    int tx = threadIdx.x & 15, ty = threadIdx.x >> 4;
    int row0 = blockIdx.x * 32 + ty * 4;
    int cb = blockIdx.y * 64;
    unsigned k0 = g_keybits[4*t];
    unsigned k1 = g_keybits[4*t + 1];
#pragma unroll
    for (int i = 0; i < 4; i++) {
        int m = row0 + i;
        int b = m >> 6;
        const float* projrow = g_proj + ((size_t)t * BS + b) * H;
#pragma unroll
        for (int p = 0; p < 2; p++) {
            float v[2];
            unpack2(acc[i][p], v[0], v[1]);
#pragma unroll
            for (int e = 0; e < 2; e++) {
                int c = cb + tx*4 + 2*p + e;
                size_t idx = (size_t)m * H + c;
                float pre = __fadd_rn(__fadd_rn(projrow[c], v[e]), b_hh[c]);
                unsigned bits = jax_random_bits32(k0, k1, (unsigned)idx);
                float nz = __fmul_rn(jax_normal_from_bits(bits), g_sxstd[c]);
                g_h[idx] = __fadd_rn(xla_tanh(pre), nz);
            }
        }
    }
}

// ============================================================================
// act = relu(h @ W1 + b1)   (32x64 tile)
// ============================================================================
__global__ void __launch_bounds__(128, 4)
ffn_kernel(const float* __restrict__ W1, const float* __restrict__ b1) {
    extern __shared__ float smem[];
    unsigned long long acc[4][2] = {};
    gemm_32x64<false>(g_h, W1, H, smem, acc);
    int tx = threadIdx.x & 15, ty = threadIdx.x >> 4;
    int row0 = blockIdx.x * 32 + ty * 4;
    int cb = blockIdx.y * 64;
#pragma unroll
    for (int i = 0; i < 4; i++) {
        int m = row0 + i;
#pragma unroll
        for (int p = 0; p < 2; p++) {
            float v[2];
            unpack2(acc[i][p], v[0], v[1]);
#pragma unroll
            for (int e = 0; e < 2; e++) {
                int c = cb + tx*4 + 2*p + e;
                g_act[(size_t)m * H + c] = fmaxf(__fadd_rn(v[e], b1[c]), 0.0f);
            }
        }
    }
}

// ============================================================================
// OLD 64x64 full-B GEMM core — proj only (runs once)
// ============================================================================
template<bool BT>
__device__ __forceinline__ void gemm_core(const float* __restrict__ A,
                                          const float* __restrict__ B,
                                          int ldb, float* smem,
                                          unsigned long long accp[4][2]) {
    float* Bsm = smem;                 // [256][68]
    float* As2 = smem + BS_FLOATS;     // [2][16][132]
    int tid = threadIdx.x;

    if (BT) {
#pragma unroll
        for (int it = 0; it < 16; it++) {
            int l = tid + 256 * it;
            int n = l & 63;
            int kq = (l >> 6) << 2;
            float4 v = *(const float4*)(B + (size_t)(blockIdx.y*64 + n)*256 + kq);
            Bsm[(kq+0)*68 + n] = v.x; Bsm[(kq+1)*68 + n] = v.y;
            Bsm[(kq+2)*68 + n] = v.z; Bsm[(kq+3)*68 + n] = v.w;
        }
    } else {
#pragma unroll
        for (int it = 0; it < 16; it++) {
            int l = tid + 256 * it;
            int k = l >> 4;
            int nq = (l & 15) << 2;
            float4 v = *(const float4*)(B + (size_t)k*ldb + blockIdx.y*64 + nq);
            *(float4*)&Bsm[k*68 + nq] = v;
        }
    }

    int arow = tid >> 2;
    int akq  = (tid & 3) << 2;
    const float* Ap = A + (size_t)(blockIdx.x*64 + arow)*256 + akq;
    int ty = tid >> 4, tx = tid & 15;

    {
        float4 av = *(const float4*)(Ap);
        float* d = As2;
        *(float2*)&d[(akq+0)*132 + arow*2] = make_float2(av.x, av.x);
        *(float2*)&d[(akq+1)*132 + arow*2] = make_float2(av.y, av.y);
        *(float2*)&d[(akq+2)*132 + arow*2] = make_float2(av.z, av.z);
        *(float2*)&d[(akq+3)*132 + arow*2] = make_float2(av.w, av.w);
    }
    __syncthreads();

    for (int c = 0; c < 16; c++) {
        float4 nv;
        if (c + 1 < 16) nv = *(const float4*)(Ap + (c+1)*16);
        const float* As = As2 + (c & 1) * (16*132);
        const float* Bc = Bsm + c * 16 * 68;
#pragma unroll
        for (int k = 0; k < 16; k++) {
            ulonglong2 bp  = *(const ulonglong2*)&Bc[k*68 + tx*4];
            ulonglong2 ad0 = *(const ulonglong2*)&As[k*132 + ty*8];
            ulonglong2 ad1 = *(const ulonglong2*)&As[k*132 + ty*8 + 4];
            fma2(accp[0][0], ad0.x, bp.x); fma2(accp[0][1], ad0.x, bp.y);
            fma2(accp[1][0], ad0.y, bp.x); fma2(accp[1][1], ad0.y, bp.y);
            fma2(accp[2][0], ad1.x, bp.x); fma2(accp[2][1], ad1.x, bp.y);
            fma2(accp[3][0], ad1.y, bp.x); fma2(accp[3][1], ad1.y, bp.y);
        }
        if (c + 1 < 16) {
            float* d = As2 + ((c+1) & 1) * (16*132);
            *(float2*)&d[(akq+0)*132 + arow*2] = make_float2(nv.x, nv.x);
            *(float2*)&d[(akq+1)*132 + arow*2] = make_float2(nv.y, nv.y);
            *(float2*)&d[(akq+2)*132 + arow*2] = make_float2(nv.z, nv.z);
            *(float2*)&d[(akq+3)*132 + arow*2] = make_float2(nv.w, nv.w);
        }
        __syncthreads();
    }
}

__device__ __forceinline__ void unpack_acc(unsigned long long accp[4][2],
                                           float acc[4][4]) {
#pragma unroll
    for (int i = 0; i < 4; i++) {
        unpack2(accp[i][0], acc[i][0], acc[i][1]);
        unpack2(accp[i][1], acc[i][2], acc[i][3]);
    }
}

// ============================================================================
// proj[t,b,:] = u[t,b,:] @ W_ih^T + b_ih  (runs once)
// ============================================================================
__global__ void __launch_bounds__(256, 2)
proj_kernel(const float* __restrict__ u, const float* __restrict__ W_ih,
            const float* __restrict__ b_ih) {
    extern __shared__ float smem[];
    unsigned long long accp[4][2] = {};
    gemm_core<true>(u, W_ih, H, smem, accp);
    float acc[4][4]; unpack_acc(accp, acc);
    int tx = threadIdx.x & 15, ty = threadIdx.x >> 4;
    int row0 = blockIdx.x * 64 + ty * 4;
    int col0 = blockIdx.y * 64 + tx * 4;
#pragma unroll
    for (int i = 0; i < 4; i++)
#pragma unroll
        for (int j = 0; j < 4; j++) {
            int c = col0 + j;
            g_proj[(size_t)(row0 + i) * H + c] = __fadd_rn(acc[i][j], b_ih[c]);
        }
}

// ============================================================================
// Fused outres (512 threads): y_hat -> out[t]; lp; log_softmax; gumbel
// argmax; resample gather. One block per batch; chunked 64x64 GEMM.
// ============================================================================
__global__ void __launch_bounds__(512, 1)
outres_kernel(const float* __restrict__ W2, const float* __restrict__ b2,
              const float* __restrict__ y, const float* __restrict__ sy,
              float* __restrict__ out, int t) {
    extern __shared__ float smem[];
    __shared__ float lp_s[NP];
    __shared__ float logw_s[NP];
    __shared__ int   I_s[NP];
    __shared__ float red_s[2];

    float* Bs = smem;              // [2][16][68]
    float* As = smem + OBS;        // [2][16][68]
    int tid = threadIdx.x;         // 0..511
    int tx = tid & 15, ty = tid >> 4;   // tx 0..15, ty 0..31
    int b = blockIdx.x;

    // Loaders (tid < 256 only): A chunk 64x16, B chunk 16x64
    int arow = tid >> 2;                 // 0..63 (tid<256)
    int akq  = (tid & 3) << 2;
    const float* Ap = g_act + (size_t)(b*64 + arow)*256 + akq;
    int bk  = tid >> 4;                  // 0..15 (tid<256)
    int bnq = (tid & 15) << 2;
    const float* Bp = W2 + (size_t)bk*OUTD + bnq;

    unsigned long long acc[2][2] = {};

    if (tid < 256) {
        float4 av = *(const float4*)(Ap);
        float4 bv = *(const float4*)(Bp);
        As[(akq+0)*68 + arow] = av.x; As[(akq+1)*68 + arow] = av.y;
        As[(akq+2)*68 + arow] = av.z; As[(akq+3)*68 + arow] = av.w;
        *(float4*)&Bs[bk*68 + bnq] = bv;
    }
    __syncthreads();

    for (int c = 0; c < 16; c++) {
        float4 av, bv;
        if (c + 1 < 16 && tid < 256) {
            av = *(const float4*)(Ap + (c+1)*16);
            bv = *(const float4*)(Bp + (size_t)(c+1)*16*OUTD);
        }
        const float* Asb = As + (c & 1) * (16*68);
        const float* Bsb = Bs + (c & 1) * (16*68);
#pragma unroll
        for (int k = 0; k < 16; k++) {
            float2 a = *(const float2*)&Asb[k*68 + ty*2];
            ulonglong2 bp = *(const ulonglong2*)&Bsb[k*68 + tx*4];
            unsigned long long a0 = dup2(a.x), a1 = dup2(a.y);
            fma2(acc[0][0], a0, bp.x); fma2(acc[0][1], a0, bp.y);
            fma2(acc[1][0], a1, bp.x); fma2(acc[1][1], a1, bp.y);
        }
        if (c + 1 < 16 && tid < 256) {
            float* Asd = As + ((c+1) & 1) * (16*68);
            Asd[(akq+0)*68 + arow] = av.x; Asd[(akq+1)*68 + arow] = av.y;
            Asd[(akq+2)*68 + arow] = av.z; Asd[(akq+3)*68 + arow] = av.w;
            float* Bsd = Bs + ((c+1) & 1) * (16*68);
            *(float4*)&Bsd[bk*68 + bnq] = bv;
        }
        __syncthreads();
    }

    // stage q[n][c] = d*d/sy into smem (overwrites GEMM smem; behind sync)
    float* q_s = smem;                 // [64][65]
#pragma unroll
    for (int i = 0; i < 2; i++) {
        int n = ty * 2 + i;
        int m = b * 64 + n;
#pragma unroll
        for (int p = 0; p < 2; p++) {
            float v[2];
            unpack2(acc[i][p], v[0], v[1]);
#pragma unroll
            for (int e = 0; e < 2; e++) {
                int c = tx*4 + 2*p + e;
                float val = __fadd_rn(v[e], b2[c]);
                out[(((size_t)t * M_ROWS) + m) * OUTD + c] = val;
                float d = __fsub_rn(val, y[(((size_t)t * BS) + b) * OUTD + c]);
                q_s[n * 65 + c] = __fdiv_rn(__fmul_rn(d, d), sy[c]);
            }
        }
    }
    __syncthreads();

    // lp[n]: XLA row-reduce (lane + lane+32, shfl tree) — identical per-n order
    int warp = tid >> 5, lane = tid & 31;
    float L = g_logdet;
#pragma unroll
    for (int k = 0; k < 4; k++) {
        int n = warp * 4 + k;
        float s = __fadd_rn(q_s[n * 65 + lane], q_s[n * 65 + lane + 32]);
#pragma unroll
        for (int off = 16; off; off >>= 1)
            s = __fadd_rn(s, __shfl_down_sync(0xffffffffu, s, off));
        if (lane == 0) lp_s[n] = __fsub_rn(-0.5f * s, L);
    }
    __syncthreads();

    if (warp == 0) {
        float m1 = fmaxf(lp_s[lane], lp_s[lane + 32]);
#pragma unroll
        for (int off = 16; off; off >>= 1)
            m1 = fmaxf(m1, __shfl_down_sync(0xffffffffu, m1, off));
        m1 = __shfl_sync(0xffffffffu, m1, 0);
        float e1 = expf(__fsub_rn(lp_s[lane], m1));
        float e2 = expf(__fsub_rn(lp_s[lane + 32], m1));
        float s = __fadd_rn(e1, e2);
#pragma unroll
        for (int off = 16; off; off >>= 1)
            s = __fadd_rn(s, __shfl_down_sync(0xffffffffu, s, off));
        if (lane == 0) { red_s[0] = m1; red_s[1] = logf(s); }
    }
    __syncthreads();
    if (tid < NP)
        logw_s[tid] = __fsub_rn(__fsub_rn(lp_s[tid], red_s[0]), red_s[1]);
    __syncthreads();

    // gumbel + logw
    float* v_s = smem;                 // [NP][NP]
    unsigned ck0 = g_keybits[4*t + 2];
    unsigned ck1 = g_keybits[4*t + 3];
    for (int l = tid; l < NP * NP; l += 512) {
        int r = l >> 6;
        int n = l & 63;
        unsigned p = (unsigned)(4096 * r + 64 * b + n);
        unsigned bits = jax_random_bits32(ck0, ck1, p);
        v_s[r * 64 + n] = __fadd_rn(jax_gumbel_from_bits(bits), logw_s[n]);
    }
    __syncthreads();

    for (int r = warp; r < NP; r += 16) {
        float v1 = v_s[r * 64 + lane];
        float v2 = v_s[r * 64 + 32 + lane];
        float val; int idx;
        if (v2 > v1) { val = v2; idx = lane + 32; }
        else         { val = v1; idx = lane; }
#pragma unroll
        for (int off = 16; off; off >>= 1) {
            float ov = __shfl_down_sync(0xffffffffu, val, off);
            int   oi = __shfl_down_sync(0xffffffffu, idx, off);
            if (ov > val || (ov == val && oi < idx)) { val = ov; idx = oi; }
        }
        if (lane == 0) I_s[r] = idx;
    }
    __syncthreads();

    const float4* hsrc = (const float4*)g_h;
    float4*       xdst = (float4*)g_x;
#pragma unroll
    for (int j = 0; j < 8; j++) {
        int lin = tid + 512 * j;       // 0..4095
        int r = lin >> 6;
        int c = lin & 63;
        int src = I_s[r];
        xdst[((size_t)(b * NP + r)) * 64 + c] =
            hsrc[((size_t)(b * NP + src)) * 64 + c];
    }
}

// ============================================================================
// Launch
// ============================================================================
extern "C" void kernel_launch(void* const* d_in, const int* in_sizes, int n_in,
                              void* d_out, int out_size) {
    const float* u    = (const float*)d_in[0];
    const float* y    = (const float*)d_in[1];
    const float* W_ih = (const float*)d_in[2];
    const float* W_hh = (const float*)d_in[3];
    const float* b_ih = (const float*)d_in[4];
    const float* b_hh = (const float*)d_in[5];
    const float* W1   = (const float*)d_in[6];
    const float* b1   = (const float*)d_in[7];
    const float* W2   = (const float*)d_in[8];
    const float* b2   = (const float*)d_in[9];
    const float* sx   = (const float*)d_in[10];
    const float* sy   = (const float*)d_in[11];
    float* out = (float*)d_out;
    (void)in_sizes; (void)n_in; (void)out_size;

    cudaFuncSetAttribute(proj_kernel,   cudaFuncAttributeMaxDynamicSharedMemorySize, SMEM_BYTES);
    cudaFuncSetAttribute(h_kernel,      cudaFuncAttributeMaxDynamicSharedMemorySize, SMEM_H_BYTES);
    cudaFuncSetAttribute(ffn_kernel,    cudaFuncAttributeMaxDynamicSharedMemorySize, SMEM_H_BYTES);
    cudaFuncSetAttribute(outres_kernel, cudaFuncAttributeMaxDynamicSharedMemorySize, SMEM_O_BYTES);

    prep_kernel<<<1, 256>>>(sx, sy);
    x0_kernel<<<STATE_ELEMS / 256, 256>>>();
    proj_kernel<<<dim3(T_STEPS * BS / 64, H / 64), 256, SMEM_BYTES>>>(u, W_ih, b_ih);

    for (int t = 0; t < T_STEPS; t++) {
        h_kernel<<<dim3(M_ROWS / 32, H / 64), 128, SMEM_H_BYTES>>>(W_hh, b_hh, t);
        ffn_kernel<<<dim3(M_ROWS / 32, H / 64), 128, SMEM_H_BYTES>>>(W1, b1);
        outres_kernel<<<BS, 512, SMEM_O_BYTES>>>(W2, b2, y, sy, out, t);
    }
}